// round 3
// baseline (speedup 1.0000x reference)
#include <cuda_runtime.h>
#include <cuda_bf16.h>
#include <cstdint>

#define N_Q 16384
#define M_R 16384
#define TPB 256
#define QT  128
#define HALVES 2
#define RHALF (M_R / HALVES)        // 8192 refs per CTA
#define TILE_REFS 128
#define TILES (RHALF / TILE_REFS)   // 64
#define RB 36                       // floats per packed ref block (144B; 36%32!=0 -> conflict-free)
#define TILE_F (TILE_REFS * RB)     // 4608 floats = 18432B per buffer

__device__ float g_wp[(size_t)M_R * RB];   // packed ref fragments (2.36 MB, L2-resident)
__device__ float g_pb[N_Q * HALVES];
__device__ int   g_pi[N_Q * HALVES];

static __device__ __forceinline__ float bfr(float v) {
    return __bfloat162float(__float2bfloat16(v));   // round-to-nearest bf16, back to f32
}
static __device__ __forceinline__ uint32_t pk(float lo, float hi) {
    __nv_bfloat162 p = __floats2bfloat162_rn(lo, hi);   // .x (lo) in low 16 bits
    return *reinterpret_cast<uint32_t*>(&p);
}
static __device__ __forceinline__ void split3(float v, float& a, float& b, float& c) {
    a = bfr(v);
    float r = v - a;      // exact
    b = bfr(r);
    c = bfr(r - b);       // residual beyond ~2^-25|v| dropped
}

// D = A*B + 0
static __device__ __forceinline__ void mma_z(float d[4], uint32_t a0, uint32_t a1,
                                             uint32_t a2, uint32_t a3,
                                             uint32_t b0, uint32_t b1) {
    asm volatile(
        "mma.sync.aligned.m16n8k16.row.col.f32.bf16.bf16.f32 "
        "{%0,%1,%2,%3},{%4,%5,%6,%7},{%8,%9},{%10,%11,%12,%13};"
        : "=f"(d[0]), "=f"(d[1]), "=f"(d[2]), "=f"(d[3])
        : "r"(a0), "r"(a1), "r"(a2), "r"(a3), "r"(b0), "r"(b1),
          "f"(0.f), "f"(0.f), "f"(0.f), "f"(0.f));
}
// D = A*B + D
static __device__ __forceinline__ void mma_a(float d[4], uint32_t a0, uint32_t a1,
                                             uint32_t a2, uint32_t a3,
                                             uint32_t b0, uint32_t b1) {
    asm volatile(
        "mma.sync.aligned.m16n8k16.row.col.f32.bf16.bf16.f32 "
        "{%0,%1,%2,%3},{%4,%5,%6,%7},{%8,%9},{%0,%1,%2,%3};"
        : "+f"(d[0]), "+f"(d[1]), "+f"(d[2]), "+f"(d[3])
        : "r"(a0), "r"(a1), "r"(a2), "r"(a3), "r"(b0), "r"(b1));
}

// ---------------- prep: pack refs into fragment order ----------------
// One thread per (ref j, col-group t). Ref block (36 floats):
//   t*8 + {0..7} = {P1a,P2a,P3a,P1b, P2b,P3b,biasv,pad}
// where Pka = pk(split_k(w[2t]),  split_k(w[2t+1]))   (cols 2t,2t+1)
//       Pkb = pk(split_k(w[2t+8]),split_k(w[2t+9]))   (cols 2t+8,2t+9)
//       biasv: t=0 -> pk(cb1,cb2); t=1 -> pk(cb3,0); else 0.  c = -0.5*||w||^2
__global__ void prep_kernel(const float* __restrict__ xb) {
    int tid = blockIdx.x * blockDim.x + threadIdx.x;
    if (tid >= M_R * 4) return;
    int j = tid >> 2, t = tid & 3;
    const float* w = xb + (size_t)j * 16;
    float s = 0.f;
#pragma unroll
    for (int d = 0; d < 16; d++) s += w[d] * w[d];
    float c = -0.5f * s;
    float cb1, cb2, cb3;
    split3(c, cb1, cb2, cb3);

    float a1[4], a2[4], a3[4];   // splits of cols {2t,2t+1,2t+8,2t+9}
    float vs[4] = { w[2 * t], w[2 * t + 1], w[2 * t + 8], w[2 * t + 9] };
#pragma unroll
    for (int i = 0; i < 4; i++) split3(vs[i], a1[i], a2[i], a3[i]);

    float* dst = g_wp + (size_t)j * RB + t * 8;
    uint32_t P[8];
    P[0] = pk(a1[0], a1[1]);
    P[1] = pk(a2[0], a2[1]);
    P[2] = pk(a3[0], a3[1]);
    P[3] = pk(a1[2], a1[3]);
    P[4] = pk(a2[2], a2[3]);
    P[5] = pk(a3[2], a3[3]);
    P[6] = (t == 0) ? pk(cb1, cb2) : (t == 1) ? pk(cb3, 0.f) : 0u;
    P[7] = 0u;
#pragma unroll
    for (int i = 0; i < 8; i++) ((uint32_t*)dst)[i] = P[i];
}

// ---------------- main kernel ----------------
// Products (A-level, B-level), 0-indexed; (2,2)=b3*b3 dropped (~2^-32):
//   (0,0)(0,1)(1,0)(0,2)(2,0)(1,1)(1,2)(2,1)  + bias block
__global__ void __launch_bounds__(TPB) nn_kernel(const float* __restrict__ x) {
    __shared__ float sm[2 * TILE_F];

    const int tid = threadIdx.x;
    const int w = tid >> 5, l = tid & 31;
    const int g = l >> 2, t = l & 3;
    const int half = blockIdx.y;

    // ---- A fragments: 12 packs Afr[row][cp][lvl] for rows g / g+8, col-pairs 2t / 2t+8
    const int q0 = blockIdx.x * QT + w * 16 + g;
    const int q1 = q0 + 8;
    uint32_t Afr[2][2][3];
#pragma unroll
    for (int r = 0; r < 2; r++) {
        const float2* row = (const float2*)(x + (size_t)(r == 0 ? q0 : q1) * 16);
        float2 va = row[t];       // cols 2t, 2t+1
        float2 vb = row[t + 4];   // cols 2t+8, 2t+9
        float s1x, s2x, s3x, s1y, s2y, s3y;
        split3(va.x, s1x, s2x, s3x);
        split3(va.y, s1y, s2y, s3y);
        Afr[r][0][0] = pk(s1x, s1y);
        Afr[r][0][1] = pk(s2x, s2y);
        Afr[r][0][2] = pk(s3x, s3y);
        split3(vb.x, s1x, s2x, s3x);
        split3(vb.y, s1y, s2y, s3y);
        Afr[r][1][0] = pk(s1x, s1y);
        Afr[r][1][1] = pk(s2x, s2y);
        Afr[r][1][2] = pk(s3x, s3y);
    }
    // bias block A values: k=128,129,130 are 1.0, rest 0
    const uint32_t a8v = (t == 0) ? 0x3F803F80u : (t == 1) ? 0x00003F80u : 0u;

    float best0 = -3.0e38f, best1 = -3.0e38f;
    int idx0 = 0, idx1 = 0;

    // preload tile 0
    {
        const uint4* src = (const uint4*)(g_wp + (size_t)(half * RHALF) * RB);
        uint4* dst = (uint4*)sm;
        for (int u = tid; u < TILE_F / 4; u += TPB) dst[u] = src[u];
    }

    for (int tile = 0; tile < TILES; tile++) {
        __syncthreads();
        if (tile + 1 < TILES) {
            const uint4* src =
                (const uint4*)(g_wp + (size_t)(half * RHALF + (tile + 1) * TILE_REFS) * RB);
            uint4* dst = (uint4*)(sm + ((tile + 1) & 1) * TILE_F);
            for (int u = tid; u < TILE_F / 4; u += TPB) dst[u] = src[u];
        }
        const float* tb = sm + (tile & 1) * TILE_F;
        const int tbase = half * RHALF + tile * TILE_REFS;

#pragma unroll 4
        for (int ch = 0; ch < 16; ch++) {
            const float* rb = tb + ch * (8 * RB) + g * RB + t * 8;
            uint4 B0 = *(const uint4*)(rb);        // P1a,P2a,P3a,P1b
            uint4 B1 = *(const uint4*)(rb + 4);    // P2b,P3b,bias,pad
            uint32_t bA0 = B0.x, bA1 = B0.y, bA2 = B0.z;   // cpA lvl 0..2
            uint32_t bB0 = B0.w, bB1 = B1.x, bB2 = B1.y;   // cpB lvl 0..2
            uint32_t bias = B1.z;

            float acc[4];
            mma_z(acc, Afr[0][0][0], Afr[1][0][0], Afr[0][1][0], Afr[1][1][0], bA0, bB0);
            mma_a(acc, Afr[0][0][0], Afr[1][0][0], Afr[0][1][0], Afr[1][1][0], bA1, bB1);
            mma_a(acc, Afr[0][0][1], Afr[1][0][1], Afr[0][1][1], Afr[1][1][1], bA0, bB0);
            mma_a(acc, Afr[0][0][0], Afr[1][0][0], Afr[0][1][0], Afr[1][1][0], bA2, bB2);
            mma_a(acc, Afr[0][0][2], Afr[1][0][2], Afr[0][1][2], Afr[1][1][2], bA0, bB0);
            mma_a(acc, Afr[0][0][1], Afr[1][0][1], Afr[0][1][1], Afr[1][1][1], bA1, bB1);
            mma_a(acc, Afr[0][0][1], Afr[1][0][1], Afr[0][1][1], Afr[1][1][1], bA2, bB2);
            mma_a(acc, Afr[0][0][2], Afr[1][0][2], Afr[0][1][2], Afr[1][1][2], bA1, bB1);
            mma_a(acc, a8v, a8v, 0u, 0u, bias, 0u);

            // epilogue: cols jb, jb+1 for rows q0 (acc0,acc1) and q1 (acc2,acc3)
            const int jb = tbase + ch * 8 + 2 * t;
            {   // pairwise (tie -> smaller j) then running (strict > keeps first)
                float pb = (acc[1] > acc[0]) ? acc[1] : acc[0];
                int   pj = (acc[1] > acc[0]) ? jb + 1 : jb;
                if (pb > best0) { best0 = pb; idx0 = pj; }
            }
            {
                float pb = (acc[3] > acc[2]) ? acc[3] : acc[2];
                int   pj = (acc[3] > acc[2]) ? jb + 1 : jb;
                if (pb > best1) { best1 = pb; idx1 = pj; }
            }
        }
    }

    // reduce across the 4 lanes of each row group (t = 0..3), tie -> smaller j
#pragma unroll
    for (int m = 1; m <= 2; m <<= 1) {
        float ob = __shfl_xor_sync(0xFFFFFFFFu, best0, m);
        int   oi = __shfl_xor_sync(0xFFFFFFFFu, idx0, m);
        if (ob > best0 || (ob == best0 && oi < idx0)) { best0 = ob; idx0 = oi; }
        ob = __shfl_xor_sync(0xFFFFFFFFu, best1, m);
        oi = __shfl_xor_sync(0xFFFFFFFFu, idx1, m);
        if (ob > best1 || (ob == best1 && oi < idx1)) { best1 = ob; idx1 = oi; }
    }
    if (t == 0) {
        g_pb[q0 * HALVES + half] = best0;
        g_pi[q0 * HALVES + half] = idx0;
        g_pb[q1 * HALVES + half] = best1;
        g_pi[q1 * HALVES + half] = idx1;
    }
}

// ---------------- merge halves (ascending, strict > == first-index argmin) ----------------
__global__ void merge_kernel(const float* __restrict__ y, float* __restrict__ out) {
    int q = blockIdx.x * blockDim.x + threadIdx.x;
    if (q >= N_Q) return;
    float b0 = g_pb[q * HALVES + 0];
    float b1 = g_pb[q * HALVES + 1];
    int i = (b1 > b0) ? g_pi[q * HALVES + 1] : g_pi[q * HALVES + 0];
    out[q] = y[i];
}

extern "C" void kernel_launch(void* const* d_in, const int* in_sizes, int n_in,
                              void* d_out, int out_size) {
    const float* x  = (const float*)d_in[0];
    const float* xb = (const float*)d_in[1];
    const float* y  = (const float*)d_in[2];
    float* out = (float*)d_out;

    prep_kernel<<<(M_R * 4) / 256, 256>>>(xb);
    dim3 grid(N_Q / QT, HALVES);   // (128, 2)
    nn_kernel<<<grid, TPB>>>(x);
    merge_kernel<<<N_Q / 256, 256>>>(y, out);
}

// round 4
// speedup vs baseline: 1.2203x; 1.2203x over previous
#include <cuda_runtime.h>
#include <cstdint>

#define N_Q 16384
#define M_R 16384
#define TPB 256
#define QPT 4
#define QBLK (TPB * QPT)        // 1024 queries per CTA column
#define NQB  (N_Q / QBLK)       // 16
#define JTILE 128
#define NJT  (M_R / JTILE)      // 128
#define WSTRIDE 18              // u64 per ref row: 16 dup-packs + bias + pad

typedef unsigned long long u64;

__device__ u64 g_wd[(size_t)M_R * WSTRIDE];   // {w_d,w_d} packs + {c,c} bias
__device__ u64 g_best[N_Q];                   // packed (sortable score | ~j)

static __device__ __forceinline__ u64 ffma2(u64 a, u64 b, u64 c) {
    u64 d;
    asm("fma.rn.f32x2 %0, %1, %2, %3;" : "=l"(d) : "l"(a), "l"(b), "l"(c));
    return d;
}
static __device__ __forceinline__ u64 pack2(float lo, float hi) {
    u64 d;
    asm("mov.b64 %0, {%1, %2};" : "=l"(d) : "f"(lo), "f"(hi));
    return d;
}
static __device__ __forceinline__ void unpack2(u64 v, float& lo, float& hi) {
    asm("mov.b64 {%0, %1}, %2;" : "=f"(lo), "=f"(hi) : "l"(v));
}
static __device__ __forceinline__ u64 enc(float s, int j) {
    uint32_t u = __float_as_uint(s);
    uint32_t key = (u & 0x80000000u) ? ~u : (u | 0x80000000u);  // monotone f32->u32
    return ((u64)key << 32) | (uint32_t)(~j);                   // tie -> smaller j wins
}

// ---- prep: duplicate-pack refs, fold bias, reset result accumulators ----
__global__ void prep_kernel(const float* __restrict__ xb) {
    int j = blockIdx.x * blockDim.x + threadIdx.x;
    if (j >= M_R) return;
    const float4* r = (const float4*)(xb + (size_t)j * 16);
    u64* dst = g_wd + (size_t)j * WSTRIDE;
    float s = 0.f;
#pragma unroll
    for (int i = 0; i < 4; i++) {
        float4 v = r[i];
        s += v.x * v.x + v.y * v.y + v.z * v.z + v.w * v.w;
        dst[4 * i + 0] = pack2(v.x, v.x);
        dst[4 * i + 1] = pack2(v.y, v.y);
        dst[4 * i + 2] = pack2(v.z, v.z);
        dst[4 * i + 3] = pack2(v.w, v.w);
    }
    float c = -0.5f * s;
    dst[16] = pack2(c, c);
    dst[17] = 0ull;
    g_best[j] = 0ull;   // key 0 == most-negative float; reset every replay
}

// ---- main scan: score = dot(x,w) - 0.5||w||^2, running argmax ----
__global__ void __launch_bounds__(TPB, 2) nn_kernel(const float* __restrict__ x,
                                                    const float* __restrict__ y_unused) {
    __shared__ u64 sw[JTILE * WSTRIDE];   // 18432 B

    const int tid = threadIdx.x;
    const int qb = blockIdx.x, jt = blockIdx.y;

    // Load j-tile (contiguous, coalesced).
    {
        const uint4* src = (const uint4*)(g_wd + (size_t)jt * JTILE * WSTRIDE);
        uint4* dst = (uint4*)sw;
        for (int u = tid; u < JTILE * WSTRIDE / 2; u += TPB) dst[u] = src[u];
    }

    // Pack this thread's 4 query rows as two query-pairs.
    const int q0 = qb * QBLK + tid;   // pairs: (q0, q0+256), (q0+512, q0+768)
    u64 PA[16], PB[16];
    {
        const float4* ra = (const float4*)(x + (size_t)q0 * 16);
        const float4* rb = (const float4*)(x + (size_t)(q0 + TPB) * 16);
        const float4* rc = (const float4*)(x + (size_t)(q0 + 2 * TPB) * 16);
        const float4* rd = (const float4*)(x + (size_t)(q0 + 3 * TPB) * 16);
#pragma unroll
        for (int i = 0; i < 4; i++) {
            float4 a = ra[i], b = rb[i], c = rc[i], d = rd[i];
            PA[4 * i + 0] = pack2(a.x, b.x);
            PA[4 * i + 1] = pack2(a.y, b.y);
            PA[4 * i + 2] = pack2(a.z, b.z);
            PA[4 * i + 3] = pack2(a.w, b.w);
            PB[4 * i + 0] = pack2(c.x, d.x);
            PB[4 * i + 1] = pack2(c.y, d.y);
            PB[4 * i + 2] = pack2(c.z, d.z);
            PB[4 * i + 3] = pack2(c.w, d.w);
        }
    }
    __syncthreads();

    float best0 = -3.0e38f, best1 = -3.0e38f, best2 = -3.0e38f, best3 = -3.0e38f;
    int i0 = 0, i1 = 0, i2 = 0, i3 = 0;
    const int jbase = jt * JTILE;

#pragma unroll 2
    for (int jj = 0; jj < JTILE; jj++) {
        const ulonglong2* row = (const ulonglong2*)(sw + jj * WSTRIDE);
        ulonglong2 wp[8];
#pragma unroll
        for (int k = 0; k < 8; k++) wp[k] = row[k];      // 8x LDS.128 (broadcast)
        u64 bias = sw[jj * WSTRIDE + 16];

        u64 acc0 = bias, acc1 = bias;
#pragma unroll
        for (int k = 0; k < 8; k++) {
            u64 w0 = wp[k].x, w1 = wp[k].y;
            acc0 = ffma2(PA[2 * k + 0], w0, acc0);       // adjacent pair shares w0 -> .reuse
            acc1 = ffma2(PB[2 * k + 0], w0, acc1);
            acc0 = ffma2(PA[2 * k + 1], w1, acc0);
            acc1 = ffma2(PB[2 * k + 1], w1, acc1);
        }
        float s0, s1, s2, s3;
        unpack2(acc0, s0, s1);   // free: register-pair aliasing
        unpack2(acc1, s2, s3);
        const int j = jbase + jj;
        if (s0 > best0) { best0 = s0; i0 = j; }          // strict > keeps first index
        if (s1 > best1) { best1 = s1; i1 = j; }
        if (s2 > best2) { best2 = s2; i2 = j; }
        if (s3 > best3) { best3 = s3; i3 = j; }
    }

    atomicMax(&g_best[q0          ], enc(best0, i0));
    atomicMax(&g_best[q0 + TPB    ], enc(best1, i1));
    atomicMax(&g_best[q0 + 2 * TPB], enc(best2, i2));
    atomicMax(&g_best[q0 + 3 * TPB], enc(best3, i3));
}

// ---- gather ----
__global__ void gather_kernel(const float* __restrict__ y, float* __restrict__ out) {
    int q = blockIdx.x * blockDim.x + threadIdx.x;
    if (q >= N_Q) return;
    u64 v = g_best[q];
    int j = (int)(~(uint32_t)v);
    out[q] = y[j];
}

extern "C" void kernel_launch(void* const* d_in, const int* in_sizes, int n_in,
                              void* d_out, int out_size) {
    const float* x  = (const float*)d_in[0];
    const float* xb = (const float*)d_in[1];
    const float* y  = (const float*)d_in[2];
    float* out = (float*)d_out;

    prep_kernel<<<M_R / 256, 256>>>(xb);
    dim3 grid(NQB, NJT);                 // 16 x 128 = 2048 CTAs
    nn_kernel<<<grid, TPB>>>(x, y);
    gather_kernel<<<N_Q / 256, 256>>>(y, out);
}

// round 5
// speedup vs baseline: 1.3808x; 1.1315x over previous
#include <cuda_runtime.h>
#include <cstdint>

#define N_Q 16384
#define M_R 16384
#define TPB 256
#define QPT 4
#define JS  18          // j-slices
#define TJ  128         // js per smem tile
typedef unsigned long long u64;

__device__ u64 g_c2[M_R];      // packed {c_j, c_j}? -> {c, 0}: dims-paired init needs {c,0}
__device__ u64 g_best[N_Q];    // packed (sortable score | ~j)

static __device__ __forceinline__ u64 ffma2(u64 a, u64 b, u64 c) {
    u64 d;
    asm("fma.rn.f32x2 %0, %1, %2, %3;" : "=l"(d) : "l"(a), "l"(b), "l"(c));
    return d;
}
static __device__ __forceinline__ u64 pack2(float lo, float hi) {
    u64 d;
    asm("mov.b64 %0, {%1, %2};" : "=l"(d) : "f"(lo), "f"(hi));
    return d;
}
static __device__ __forceinline__ void unpack2(u64 v, float& lo, float& hi) {
    asm("mov.b64 {%0, %1}, %2;" : "=f"(lo), "=f"(hi) : "l"(v));
}
static __device__ __forceinline__ u64 enc(float s, int j) {
    uint32_t u = __float_as_uint(s);
    uint32_t key = (u & 0x80000000u) ? ~u : (u | 0x80000000u);  // monotone f32 -> u32
    return ((u64)key << 32) | (uint32_t)(~j);                   // tie -> smaller j wins
}

// ---- prep: bias {c,0}, reset accumulators ----
__global__ void prep_kernel(const float* __restrict__ xb) {
    int j = blockIdx.x * blockDim.x + threadIdx.x;
    if (j >= M_R) return;
    const float4* r = (const float4*)(xb + (size_t)j * 16);
    float s = 0.f;
#pragma unroll
    for (int i = 0; i < 4; i++) {
        float4 v = r[i];
        s += v.x * v.x + v.y * v.y + v.z * v.z + v.w * v.w;
    }
    g_c2[j] = pack2(-0.5f * s, 0.0f);
    g_best[j] = 0ull;               // key 0 == most-negative; reset every replay (N_Q==M_R)
}

// ---- main scan ----
__global__ void __launch_bounds__(TPB, 2) nn_kernel(const float* __restrict__ x,
                                                    const float* __restrict__ xb) {
    __shared__ float4 s_w[TJ * 4];
    __shared__ u64    s_c[TJ];

    const int qb  = blockIdx.x;
    const int sl  = blockIdx.y;
    const int j0  = (sl * M_R) / JS;
    const int j1  = ((sl + 1) * M_R) / JS;
    const int tid = threadIdx.x;

    // Load QPT query rows, dims paired: xr[k][p] = {x[2p], x[2p+1]}
    u64 xr[QPT][8];
    int qidx[QPT];
#pragma unroll
    for (int k = 0; k < QPT; k++) {
        int q = qb * (TPB * QPT) + k * TPB + tid;
        qidx[k] = q;
        const float4* r = (const float4*)(x + (size_t)q * 16);
#pragma unroll
        for (int i = 0; i < 4; i++) {
            float4 v = r[i];
            xr[k][i * 2 + 0] = pack2(v.x, v.y);
            xr[k][i * 2 + 1] = pack2(v.z, v.w);
        }
    }

    float best[QPT];
    int   bidx[QPT];
#pragma unroll
    for (int k = 0; k < QPT; k++) { best[k] = -3.0e38f; bidx[k] = 0; }

    for (int jt = j0; jt < j1; jt += TJ) {
        int cnt = min(TJ, j1 - jt);
        __syncthreads();
        for (int t = tid; t < cnt * 4; t += TPB)
            s_w[t] = ((const float4*)xb)[jt * 4 + t];
        for (int t = tid; t < cnt; t += TPB)
            s_c[t] = g_c2[jt + t];
        __syncthreads();

        const u64* w8 = (const u64*)s_w;   // 8 u64 dim-pairs per j
#pragma unroll 2
        for (int jj = 0; jj < cnt; jj++) {
            u64 wp[8];
#pragma unroll
            for (int p = 0; p < 8; p++) wp[p] = w8[jj * 8 + p];   // 4x LDS.128
            const u64 ini = s_c[jj];

            u64 acc[QPT];
#pragma unroll
            for (int k = 0; k < QPT; k++) acc[k] = ini;
            // query-inner: 4 consecutive FFMA2 share wp[p] in the b slot -> .reuse
#pragma unroll
            for (int p = 0; p < 8; p++) {
#pragma unroll
                for (int k = 0; k < QPT; k++)
                    acc[k] = ffma2(xr[k][p], wp[p], acc[k]);
            }
            const int j = jt + jj;
#pragma unroll
            for (int k = 0; k < QPT; k++) {
                float lo, hi;
                unpack2(acc[k], lo, hi);
                float s = lo + hi;
                if (s > best[k]) { best[k] = s; bidx[k] = j; }   // strict > == first index
            }
        }
    }

#pragma unroll
    for (int k = 0; k < QPT; k++)
        atomicMax(&g_best[qidx[k]], enc(best[k], bidx[k]));
}

// ---- gather ----
__global__ void gather_kernel(const float* __restrict__ y, float* __restrict__ out) {
    int q = blockIdx.x * blockDim.x + threadIdx.x;
    if (q >= N_Q) return;
    u64 v = g_best[q];
    int j = (int)(~(uint32_t)v);
    out[q] = y[j];
}

extern "C" void kernel_launch(void* const* d_in, const int* in_sizes, int n_in,
                              void* d_out, int out_size) {
    const float* x  = (const float*)d_in[0];
    const float* xb = (const float*)d_in[1];
    const float* y  = (const float*)d_in[2];
    float* out = (float*)d_out;

    prep_kernel<<<M_R / 256, 256>>>(xb);
    dim3 grid(N_Q / (TPB * QPT), JS);   // 16 x 18 = 288 CTAs, single wave at occ 2
    nn_kernel<<<grid, TPB>>>(x, xb);
    gather_kernel<<<N_Q / 256, 256>>>(y, out);
}